// round 10
// baseline (speedup 1.0000x reference)
#include <cuda_runtime.h>

#define BATCH 8
#define SEQ   2048
#define VDIM  64
#define CHUNK 32
#define NCHUNK (SEQ / CHUNK)    // 64
#define NBLK   (BATCH * NCHUNK) // 512
#define THREADS 512
#define NQ    16                 // float4 quads across VDIM
#define NSEG  32                 // 1 row per segment

// Scratch (__device__ globals per allocation-free rule)
__device__ float4 g_csum4[NBLK * NQ];   // per-chunk channel sums of v_j (j>=1)
__device__ int    g_cnt[BATCH];         // arrival counters (zeroed each launch)

__device__ __forceinline__ float4 f4add(float4 a, float4 b) {
    return make_float4(a.x + b.x, a.y + b.y, a.z + b.z, a.w + b.w);
}
__device__ __forceinline__ float4 f4sub(float4 a, float4 b) {
    return make_float4(a.x - b.x, a.y - b.y, a.z - b.z, a.w - b.w);
}
__device__ __forceinline__ float4 f4mul(float4 a, float4 b) {
    return make_float4(a.x * b.x, a.y * b.y, a.z * b.z, a.w * b.w);
}
__device__ __forceinline__ float4 f4fma(float s, float4 a, float4 acc) {
    return make_float4(fmaf(s, a.x, acc.x), fmaf(s, a.y, acc.y),
                       fmaf(s, a.z, acc.z), fmaf(s, a.w, acc.w));
}

__global__ __launch_bounds__(THREADS, 4) void kF(
    const float* __restrict__ h,
    const float* __restrict__ wv,
    const float* __restrict__ wv_bos,
    const float* __restrict__ wo_w,
    const float* __restrict__ qk_dir,
    const float* __restrict__ qk_bos,
    const float* __restrict__ qk_prev,
    float* __restrict__ out)
{
    __shared__ float4 hs4[CHUNK * NQ];    // 8 KB raw h tile
    __shared__ float4 part4[NSEG][NQ];    // 8 KB per-row value vectors
    __shared__ float4 ppre[NSEG][NQ];     // 8 KB prefix partials
    __shared__ float4 w4s[CHUNK];         // 512 B per-row softmax weights
    __shared__ float  qbs[VDIM], qps[VDIM], v0s[VDIM];
    __shared__ float  sd0;

    const int b    = blockIdx.x / NCHUNK;
    const int k    = blockIdx.x % NCHUNK;
    const int tid  = threadIdx.x;
    const int q    = tid & 15;    // channel quad
    const int s    = tid >> 4;    // row within chunk (0..31)
    const int lane = tid & 31;
    const int w    = tid >> 5;    // warp 0..15

    const float*  hb  = h + (size_t)b * SEQ * VDIM;
    const float4* hb4 = reinterpret_cast<const float4*>(hb);
    const int i0 = k * CHUNK;
    const float4 wv4 = reinterpret_cast<const float4*>(wv)[q];
    const float4 zero = make_float4(0.f, 0.f, 0.f, 0.f);

    // ---- phase 1: one LDG.128 per thread ----
    const float4 hr = hb4[(size_t)(i0 + s) * NQ + q];
    hs4[s * NQ + q] = hr;
    const float4 pv = f4mul(hr, wv4);                 // v_i for my row
    part4[s][q] = (k == 0 && s == 0) ? zero : pv;     // exclude global row 0

    float4 vm1 = zero;
    if (s == 0 && k > 0)
        vm1 = f4mul(hb4[(size_t)(i0 - 1) * NQ + q], wv4);

    // stage q vectors
    if (tid < VDIM) { qbs[tid] = qk_bos[tid]; qps[tid] = qk_prev[tid]; }

    // d0 = h[b,0,:] . qk_dir (warp 0)
    if (w == 0) {
        float pd = hb[lane] * qk_dir[lane] + hb[lane + 32] * qk_dir[lane + 32];
        #pragma unroll
        for (int o = 16; o > 0; o >>= 1) pd += __shfl_xor_sync(0xffffffffu, pd, o);
        if (lane == 0) sd0 = pd;
    }

    // v0 = wo_w @ wv_bos (threads 64..127, one output channel each)
    if (tid >= 64 && tid < 64 + VDIM) {
        const int co = tid - 64;
        const float4* wrow = reinterpret_cast<const float4*>(wo_w + co * VDIM);
        const float4* wb4  = reinterpret_cast<const float4*>(wv_bos);
        float p = 0.f;
        #pragma unroll
        for (int j = 0; j < NQ; j++) {
            float4 a = wrow[j], bb = wb4[j];
            p += a.x * bb.x + a.y * bb.y + a.z * bb.z + a.w * bb.w;
        }
        v0s[co] = p;
    }
    __syncthreads();   // sync1: tile, part, q vecs, sd0, v0 ready

    if (s > 0) vm1 = f4mul(hs4[(s - 1) * NQ + q], wv4);

    // ---- publish chunk aggregate (16 threads, one quad each) ----
    if (tid < NQ) {
        float4 a = part4[0][tid];
        #pragma unroll
        for (int sp = 1; sp < NSEG; sp++) a = f4add(a, part4[sp][tid]);
        g_csum4[blockIdx.x * NQ + tid] = a;
        __threadfence();
    }
    __syncthreads();   // sync2: publish + fence done
    if (tid == 0) atomicAdd(&g_cnt[b], 1);

    // ---- dots + weights: warp w handles rows 2w, 2w+1 ----
    {
        const float* hsf = reinterpret_cast<const float*>(hs4);
        const float qbl = qbs[lane], qbh = qbs[lane + 32];
        const float qpl = qps[lane], qph = qps[lane + 32];
        const float d0  = sd0;
        #pragma unroll
        for (int rr = 0; rr < 2; rr++) {
            const int r = w * 2 + rr;
            float hl = hsf[r * VDIM + lane];
            float hh = hsf[r * VDIM + lane + 32];
            float pa = hl * qbl + hh * qbh;
            float ps = hl * qpl + hh * qph;
            #pragma unroll
            for (int o = 16; o > 0; o >>= 1) {
                pa += __shfl_xor_sync(0xffffffffu, pa, o);
                ps += __shfl_xor_sync(0xffffffffu, ps, o);
            }
            if (lane == 0) {
                const int i = i0 + r;
                const float a = pa * d0;   // column-0 logit
                const float sl = ps;       // sub-diagonal logit
                float4 wt;
                if (i == 0) {
                    wt = make_float4(1.f, 0.f, 0.f, 0.f);
                } else if (i == 1) {
                    float t  = a + sl;
                    float m  = fmaxf(t, 0.f);
                    float e  = __expf(t - m);
                    float e1 = __expf(-m);
                    float inv = 1.f / (e + e1);
                    wt = make_float4(e * inv, 0.f, e1 * inv, 0.f);
                } else {
                    float m  = fmaxf(fmaxf(a, sl), 0.f);
                    float ea = __expf(a - m);
                    float es = __expf(sl - m);
                    float e0 = __expf(-m);
                    float inv = 1.f / (ea + es + e0 * (float)(i - 1));
                    wt = make_float4(ea * inv, es * inv, e0 * inv, 0.f);
                }
                w4s[r] = wt;
            }
        }
    }

    // ---- wait for all aggregates of this batch (arrive-before-poll, safe) ----
    if (tid == 0 && k > 0) {
        volatile int* cp = &g_cnt[b];
        while (*cp < NCHUNK) __nanosleep(32);
        __threadfence();
    }
    __syncthreads();   // sync3: weights ready AND poll passed

    // ---- cross-chunk prefix: 2 predicated LDG.128 per thread ----
    {
        float4 x = zero;
        if (s < k)      x = g_csum4[(b * NCHUNK + s) * NQ + q];
        if (s + 32 < k) x = f4add(x, g_csum4[(b * NCHUNK + s + 32) * NQ + q]);
        ppre[s][q] = x;
    }
    __syncthreads();   // sync4

    float4 Sb = ppre[0][q];
    #pragma unroll
    for (int sp = 1; sp < NSEG; sp++) Sb = f4add(Sb, ppre[sp][q]);
    #pragma unroll
    for (int sp = 0; sp < NSEG - 1; sp++)
        if (sp < s) Sb = f4add(Sb, part4[sp][q]);   // rows of this chunk before mine

    // ---- 1-step recurrence ----
    float4 S2 = f4sub(Sb, vm1);          // sum_{1..i-2}
    if (k == 0 && s == 1) S2 = zero;     // row 1 special (vm1 slot is fake v_0)
    const float4 wt = w4s[s];
    const float4 v04 = reinterpret_cast<const float4*>(v0s)[q];
    float4 o = f4fma(wt.x, v04, zero);
    o = f4fma(wt.y, vm1, o);
    o = f4fma(wt.z, f4add(S2, pv), o);

    float4* ob4 = reinterpret_cast<float4*>(out + (size_t)b * SEQ * VDIM);
    ob4[(size_t)(i0 + s) * NQ + q] = o;
}

// ---------------------------------------------------------------------------
extern "C" void kernel_launch(void* const* d_in, const int* in_sizes, int n_in,
                              void* d_out, int out_size)
{
    const float* h        = (const float*)d_in[0];
    // d_in[1], d_in[2]: mask_one / mask_zero — causal structure hardcoded
    const float* wv_bos   = (const float*)d_in[3];
    const float* wv       = (const float*)d_in[4];
    const float* wo_w     = (const float*)d_in[5];
    const float* qk_dir   = (const float*)d_in[6];
    const float* qk_bos   = (const float*)d_in[7];
    const float* qk_prev  = (const float*)d_in[8];
    float* out = (float*)d_out;

    void* cnt_ptr = nullptr;
    cudaGetSymbolAddress(&cnt_ptr, g_cnt);
    cudaMemsetAsync(cnt_ptr, 0, sizeof(int) * BATCH);

    kF<<<NBLK, THREADS>>>(h, wv, wv_bos, wo_w, qk_dir, qk_bos, qk_prev, out);
}

// round 11
// speedup vs baseline: 1.6115x; 1.6115x over previous
#include <cuda_runtime.h>

#define BATCH 8
#define SEQ   2048
#define VDIM  64
#define CHUNK 256
#define NCHUNK (SEQ / CHUNK)    // 8
#define NBLK   (BATCH * NCHUNK) // 64
#define THREADS 512
#define NQ    16                 // float4 quads across VDIM
#define NGRP  32                 // row groups per chunk
#define RPG   (CHUNK / NGRP)     // 8 rows per group

__device__ __forceinline__ float4 f4add(float4 a, float4 b) {
    return make_float4(a.x + b.x, a.y + b.y, a.z + b.z, a.w + b.w);
}
__device__ __forceinline__ float4 f4sub(float4 a, float4 b) {
    return make_float4(a.x - b.x, a.y - b.y, a.z - b.z, a.w - b.w);
}
__device__ __forceinline__ float4 f4mul(float4 a, float4 b) {
    return make_float4(a.x * b.x, a.y * b.y, a.z * b.z, a.w * b.w);
}
__device__ __forceinline__ float4 f4fma(float s, float4 a, float4 acc) {
    return make_float4(fmaf(s, a.x, acc.x), fmaf(s, a.y, acc.y),
                       fmaf(s, a.z, acc.z), fmaf(s, a.w, acc.w));
}
__device__ __forceinline__ float4 shfl_up4(float4 v, int o) {
    return make_float4(__shfl_up_sync(0xffffffffu, v.x, o),
                       __shfl_up_sync(0xffffffffu, v.y, o),
                       __shfl_up_sync(0xffffffffu, v.z, o),
                       __shfl_up_sync(0xffffffffu, v.w, o));
}
__device__ __forceinline__ float4 shfl_xor4(float4 v, int o) {
    return make_float4(__shfl_xor_sync(0xffffffffu, v.x, o),
                       __shfl_xor_sync(0xffffffffu, v.y, o),
                       __shfl_xor_sync(0xffffffffu, v.z, o),
                       __shfl_xor_sync(0xffffffffu, v.w, o));
}

struct SmLayout {
    float4 hs4[CHUNK * NQ];    // 64 KB raw h tile
    float4 pre[NGRP][NQ];      // 8 KB preceding-row partial sums (x wv)
    float4 part4[NGRP][NQ];    // 8 KB own-group value sums (x wv)
    float4 gpre[NGRP][NQ];     // 8 KB total exclusive prefix per group
    float4 w4s[CHUNK];         // 4 KB per-row softmax weights
    float  dpa[CHUNK][2];      // dot partials (qk_bos)
    float  dps[CHUNK][2];      // dot partials (qk_prev)
    float  qbs[VDIM], qps[VDIM], v0s[VDIM];
    float  sd0;
};

extern __shared__ char smem_raw[];

__global__ __launch_bounds__(THREADS, 1) void kF(
    const float* __restrict__ h,
    const float* __restrict__ wv,
    const float* __restrict__ wv_bos,
    const float* __restrict__ wo_w,
    const float* __restrict__ qk_dir,
    const float* __restrict__ qk_bos,
    const float* __restrict__ qk_prev,
    float* __restrict__ out)
{
    SmLayout* sm = reinterpret_cast<SmLayout*>(smem_raw);

    const int b    = blockIdx.x / NCHUNK;
    const int k    = blockIdx.x % NCHUNK;
    const int tid  = threadIdx.x;
    const int q    = tid & 15;    // channel quad
    const int g    = tid >> 4;    // row group 0..31 (8 rows each)
    const int lane = tid & 31;
    const int w    = tid >> 5;    // warp 0..15

    const float*  hb  = h + (size_t)b * SEQ * VDIM;
    const float4* hb4 = reinterpret_cast<const float4*>(hb);
    const int i0 = k * CHUNK;
    const float4 wv4  = reinterpret_cast<const float4*>(wv)[q];
    const float4 zero = make_float4(0.f, 0.f, 0.f, 0.f);

    // ---- phase A: redundant prefix read — sum preceding rows [1, i0) ----
    {
        float4 pacc = zero;
        const int m_end = k * 8;      // rows jj = g + 32*m, jj < i0
        #pragma unroll 4
        for (int m = 0; m < m_end; m++) {
            const int jj = g + 32 * m;
            if (jj != 0)              // exclude global row 0
                pacc = f4add(pacc, hb4[(size_t)jj * NQ + q]);
        }
        sm->pre[g][q] = f4mul(pacc, wv4);
    }

    // ---- phase B: own tile (8 rows per thread) + group value sums ----
    float4 hr[RPG];
    {
        const int rbase = g * RPG;
        float4 gs = zero;
        #pragma unroll
        for (int rr = 0; rr < RPG; rr++) {
            hr[rr] = hb4[(size_t)(i0 + rbase + rr) * NQ + q];
            sm->hs4[(rbase + rr) * NQ + q] = hr[rr];
            if (!(k == 0 && g == 0 && rr == 0)) gs = f4add(gs, hr[rr]);
        }
        sm->part4[g][q] = f4mul(gs, wv4);
    }

    // stage q vectors
    if (tid < VDIM) { sm->qbs[tid] = qk_bos[tid]; sm->qps[tid] = qk_prev[tid]; }

    // d0 = h[b,0,:] . qk_dir (warp 0)
    if (w == 0) {
        float pd = hb[lane] * qk_dir[lane] + hb[lane + 32] * qk_dir[lane + 32];
        #pragma unroll
        for (int o = 16; o > 0; o >>= 1) pd += __shfl_xor_sync(0xffffffffu, pd, o);
        if (lane == 0) sm->sd0 = pd;
    }

    // v0 = wo_w @ wv_bos (threads 64..127, one output channel each)
    if (tid >= 64 && tid < 64 + VDIM) {
        const int co = tid - 64;
        const float4* wrow = reinterpret_cast<const float4*>(wo_w + co * VDIM);
        const float4* wb4  = reinterpret_cast<const float4*>(wv_bos);
        float p = 0.f;
        #pragma unroll
        for (int j = 0; j < NQ; j++) {
            float4 a = wrow[j], bb = wb4[j];
            p += a.x * bb.x + a.y * bb.y + a.z * bb.z + a.w * bb.w;
        }
        sm->v0s[co] = p;
    }
    __syncthreads();   // S1: hs4, pre, part4, q vecs, sd0, v0 ready

    // ---- scan: warp w owns quad w; lane = group ----
    {
        const int qq = w;
        // total of preceding-rows partials (reduce over 32 groups)
        float4 tot = sm->pre[lane][qq];
        #pragma unroll
        for (int o = 16; o > 0; o >>= 1) tot = f4add(tot, shfl_xor4(tot, o));
        // exclusive scan of own-chunk group sums
        const float4 pv = sm->part4[lane][qq];
        float4 inc = pv;
        #pragma unroll
        for (int o = 1; o < 32; o <<= 1) {
            float4 t = shfl_up4(inc, o);
            if (lane >= o) inc = f4add(inc, t);
        }
        sm->gpre[lane][qq] = f4add(tot, f4sub(inc, pv));
    }

    // ---- dots: 2 threads per row, staggered conflict-free smem reads ----
    {
        const float* hsf = reinterpret_cast<const float*>(sm->hs4);
        const int r    = tid & 255;
        const int half = tid >> 8;
        float a0 = 0.f, a1 = 0.f, s0 = 0.f, s1 = 0.f;
        #pragma unroll
        for (int j0 = 0; j0 < 32; j0 += 2) {
            int ja = half * 32 + ((j0 + tid) & 31);
            int jb = half * 32 + ((j0 + 1 + tid) & 31);
            float ha  = hsf[r * VDIM + ja];
            float hb2 = hsf[r * VDIM + jb];
            a0 += ha  * sm->qbs[ja];  s0 += ha  * sm->qps[ja];
            a1 += hb2 * sm->qbs[jb];  s1 += hb2 * sm->qps[jb];
        }
        sm->dpa[r][half] = a0 + a1;
        sm->dps[r][half] = s0 + s1;
    }
    __syncthreads();   // S2: dot partials + gpre ready

    // ---- weights: one thread per row ----
    if (tid < CHUNK) {
        const int r = tid;
        const int i = i0 + r;
        const float a = (sm->dpa[r][0] + sm->dpa[r][1]) * sm->sd0;  // col-0 logit
        const float s =  sm->dps[r][0] + sm->dps[r][1];             // sub-diag logit
        float4 wt;
        if (i == 0) {
            wt = make_float4(1.f, 0.f, 0.f, 0.f);
        } else if (i == 1) {
            float t  = a + s;
            float m  = fmaxf(t, 0.f);
            float e  = __expf(t - m);
            float e1 = __expf(-m);
            float inv = 1.f / (e + e1);
            wt = make_float4(e * inv, 0.f, e1 * inv, 0.f);
        } else {
            float m  = fmaxf(fmaxf(a, s), 0.f);
            float ea = __expf(a - m);
            float es = __expf(s - m);
            float e0 = __expf(-m);
            float inv = 1.f / (ea + es + e0 * (float)(i - 1));
            wt = make_float4(ea * inv, es * inv, e0 * inv, 0.f);
        }
        sm->w4s[r] = wt;
    }
    __syncthreads();   // S3: weights ready

    // ---- recurrence: 8 rows per thread ----
    const int rbase = g * RPG;
    float4 vm1 = zero;
    if (g == 0) {
        if (k > 0) vm1 = f4mul(hb4[(size_t)(i0 - 1) * NQ + q], wv4);
    } else {
        vm1 = f4mul(sm->hs4[(rbase - 1) * NQ + q], wv4);
    }
    float4 S2 = f4sub(sm->gpre[g][q], vm1);
    const float4 v04 = reinterpret_cast<const float4*>(sm->v0s)[q];
    float4* ob4 = reinterpret_cast<float4*>(out + (size_t)b * SEQ * VDIM);
    #pragma unroll
    for (int rr = 0; rr < RPG; rr++) {
        const float4 wt = sm->w4s[rbase + rr];
        const float4 vi = f4mul(hr[rr], wv4);
        float4 o = f4fma(wt.x, v04, zero);
        o = f4fma(wt.y, vm1, o);
        o = f4fma(wt.z, f4add(S2, vi), o);
        ob4[(size_t)(i0 + rbase + rr) * NQ + q] = o;
        S2 = f4add(S2, vm1);
        vm1 = vi;
        if (k == 0 && g == 0 && rr < 2) S2 = zero;   // rows 0,1 special
    }
}

// ---------------------------------------------------------------------------
extern "C" void kernel_launch(void* const* d_in, const int* in_sizes, int n_in,
                              void* d_out, int out_size)
{
    const float* h        = (const float*)d_in[0];
    // d_in[1], d_in[2]: mask_one / mask_zero — causal structure hardcoded
    const float* wv_bos   = (const float*)d_in[3];
    const float* wv       = (const float*)d_in[4];
    const float* wo_w     = (const float*)d_in[5];
    const float* qk_dir   = (const float*)d_in[6];
    const float* qk_bos   = (const float*)d_in[7];
    const float* qk_prev  = (const float*)d_in[8];
    float* out = (float*)d_out;

    static bool attr_set = false;
    if (!attr_set) {
        cudaFuncSetAttribute(kF, cudaFuncAttributeMaxDynamicSharedMemorySize,
                             (int)sizeof(SmLayout));
        attr_set = true;
    }

    kF<<<NBLK, THREADS, sizeof(SmLayout)>>>(
        h, wv, wv_bos, wo_w, qk_dir, qk_bos, qk_prev, out);
}